// round 16
// baseline (speedup 1.0000x reference)
#include <cuda_runtime.h>

// PointPillarScatter: out[b,c,yi,xi] = feat[b,c,n*] where n* = max point index
// mapping to cell (yi,xi) in batch b (JAX scatter-set last-wins); 0 elsewhere.
// Index math replicates XLA: /0.16f -> *fp32(1/0.16f) == *6.25f exactly.
//
// R15 (cooperative 256B-row gathers + SMEM re-order) with the fill role
// software-pipelined over 2 tiles per block (double-buffered SMEM):
//   A(t0) -> sync -> [gathers A(t1) issued first, then B(t0) stores] ->
//   sync -> B(t1)
// overlapping gather latency with SMEM/store work inside each block.
// Pipeline: L0 init||min, L1 winner||T(b0), Lk T(bk)||F(bk-1), L4 F(b3).

namespace {
constexpr int B  = 4;
constexpr int C  = 64;
constexpr int N  = 100000;
constexpr int NY = 496;
constexpr int NX = 432;
constexpr int CELLS  = NY * NX;        // 214272
constexpr int VCELLS = CELLS / 4;      // 53568 (float4 granularity)
constexpr int NV     = N / 4;          // 25000 point-quads per channel

constexpr int T_PB    = (N + 63) / 64;     // 1563 transpose tiles per batch
constexpr int F_PAIRS = CELLS / 128;       // 1674 fill tile-pairs (exact)
constexpr int TF_BLOCKS = T_PB + F_PAIRS;  // 3237

constexpr int I_BLOCKS = (B * VCELLS + 255) / 256;   // 837 init blocks
constexpr int M_PB     = 98;                          // min blocks per batch
constexpr int M_BLOCKS = M_PB * B;                    // 392
constexpr int W_PB     = (N + 255) / 256;             // 391 winner blocks/batch
constexpr int W_BLOCKS = W_PB * B;                    // 1564
}

// Scratch (no runtime allocation allowed).
__device__ __align__(16) int   g_winner[B * CELLS];
__device__ float g_minxy[B][2];
__device__ __align__(16) float g_buf[2][(size_t)N * C];   // 2 x 25.6 MB row-major

__device__ __forceinline__ void atomicMinF(float* addr, float v) {
    if (v >= 0.0f) atomicMin((int*)addr, __float_as_int(v));
    else           atomicMax((unsigned int*)addr, __float_as_uint(v));
}

// ── L0: init || min ──────────────────────────────────────────────────────
__device__ __forceinline__ void init_body(int blk) {
    int i = blk * 256 + threadIdx.x;
    if (i < B * VCELLS) reinterpret_cast<int4*>(g_winner)[i] = make_int4(-1, -1, -1, -1);
    if (i < B * 2) reinterpret_cast<float*>(g_minxy)[i] = __int_as_float(0x7f800000);
}

__device__ __forceinline__ void min_body(const float4* __restrict__ pts, int blk) {
    const int b = blk / M_PB;
    const int bx = blk % M_PB;
    const float INF = __int_as_float(0x7f800000);
    float mx = INF, my = INF;
    for (int n = bx * 256 + threadIdx.x; n < N; n += M_PB * 256) {
        float4 v = pts[b * N + n];
        mx = fminf(mx, v.y);
        my = fminf(my, v.z);
    }
    #pragma unroll
    for (int o = 16; o; o >>= 1) {
        mx = fminf(mx, __shfl_xor_sync(0xffffffffu, mx, o));
        my = fminf(my, __shfl_xor_sync(0xffffffffu, my, o));
    }
    __shared__ float sx[8], sy[8];
    const int warp = threadIdx.x >> 5, lane = threadIdx.x & 31;
    if (lane == 0) { sx[warp] = mx; sy[warp] = my; }
    __syncthreads();
    if (warp == 0) {
        mx = (lane < 8) ? sx[lane] : INF;
        my = (lane < 8) ? sy[lane] : INF;
        #pragma unroll
        for (int o = 4; o; o >>= 1) {
            mx = fminf(mx, __shfl_xor_sync(0xffffffffu, mx, o));
            my = fminf(my, __shfl_xor_sync(0xffffffffu, my, o));
        }
        if (lane == 0) {
            atomicMinF(&g_minxy[b][0], mx);
            atomicMinF(&g_minxy[b][1], my);
        }
    }
}

__global__ void __launch_bounds__(256) pp_initmin(const float4* __restrict__ pts) {
    const int bx = blockIdx.x;
    if (bx < I_BLOCKS) init_body(bx);
    else               min_body(pts, bx - I_BLOCKS);
}

// ── Winner role (last-wins via atomicMax on point index) ─────────────────
__device__ __forceinline__ void w_body(const float4* __restrict__ pts, int blk) {
    const int b = blk / W_PB;
    const int n = (blk % W_PB) * 256 + threadIdx.x;
    if (n >= N) return;
    float4 v = pts[b * N + n];
    const float R = 6.25f;                 // fp32(1/0.16f) == 6.25f (XLA rewrite)
    int xi = (int)floorf((v.y - g_minxy[b][0]) * R);
    int yi = (int)floorf((v.z - g_minxy[b][1]) * R);
    xi = min(max(xi, 0), NX - 1);
    yi = min(max(yi, 0), NY - 1);
    atomicMax(&g_winner[b * CELLS + yi * NX + xi], n);
}

// ── Transpose role: 64-point x 64-channel SMEM tile (pad-65). ────────────
__device__ __forceinline__ void t_body(const float* __restrict__ feat, int b,
                                       int blk, float* S) {
    const int t = threadIdx.x;
    const int n0 = blk * 64;
    const float4* f4 = reinterpret_cast<const float4*>(feat);
    #pragma unroll
    for (int i = 0; i < 4; ++i) {
        int item = i * 256 + t;            // 1024 items
        int c = item >> 4;                 // channel 0..63
        int j = item & 15;                 // f4 index within 64 points
        int nf = (n0 >> 2) + j;
        if (nf < NV) {
            float4 v = __ldcs(f4 + ((size_t)b * C + c) * NV + nf);
            int nl = j * 4;
            S[(nl + 0) * 65 + c] = v.x;
            S[(nl + 1) * 65 + c] = v.y;
            S[(nl + 2) * 65 + c] = v.z;
            S[(nl + 3) * 65 + c] = v.w;
        }
    }
    __syncthreads();
    float4* o = reinterpret_cast<float4*>(g_buf[b & 1]);
    #pragma unroll
    for (int i = 0; i < 4; ++i) {
        int item = i * 256 + t;
        int nl = item >> 4;                // local point 0..63
        int cf = item & 15;                // channel f4 0..15
        int n = n0 + nl;
        if (n < N) {
            float4 v = make_float4(S[nl * 65 + 4 * cf + 0],
                                   S[nl * 65 + 4 * cf + 1],
                                   S[nl * 65 + 4 * cf + 2],
                                   S[nl * 65 + 4 * cf + 3]);
            o[(size_t)n * 16 + cf] = v;
        }
    }
}

// ── Fill helpers ─────────────────────────────────────────────────────────
__device__ __forceinline__ void f_gather(const float4* __restrict__ fp,
                                         const int* w_s, float4* g) {
    const int t = threadIdx.x;
    const float4 z = make_float4(0.f, 0.f, 0.f, 0.f);
    #pragma unroll
    for (int i = 0; i < 4; ++i) {
        int item = i * 256 + t;
        int cell  = item >> 4;             // 0..63
        int chunk = item & 15;             // channel f4 0..15
        int n = w_s[cell];
        g[i] = (n >= 0) ? __ldg(fp + (size_t)n * 16 + chunk) : z;
    }
}

__device__ __forceinline__ void f_stage(float* S, const float4* g) {
    const int t = threadIdx.x;
    #pragma unroll
    for (int i = 0; i < 4; ++i) {
        int item = i * 256 + t;
        int cell  = item >> 4;
        int chunk = item & 15;
        S[cell * 65 + 4 * chunk + 0] = g[i].x;
        S[cell * 65 + 4 * chunk + 1] = g[i].y;
        S[cell * 65 + 4 * chunk + 2] = g[i].z;
        S[cell * 65 + 4 * chunk + 3] = g[i].w;
    }
}

__device__ __forceinline__ void f_store(float4* __restrict__ out, int b,
                                        int q0, const float* S) {
    const int t = threadIdx.x;
    #pragma unroll
    for (int i = 0; i < 4; ++i) {
        int item = i * 256 + t;
        int c = item >> 4;                 // channel 0..63
        int j = item & 15;                 // cell f4 0..15
        float4 v = make_float4(S[(4 * j + 0) * 65 + c],
                               S[(4 * j + 1) * 65 + c],
                               S[(4 * j + 2) * 65 + c],
                               S[(4 * j + 3) * 65 + c]);
        __stcs(out + ((size_t)b * C + c) * VCELLS + q0 + j, v);
    }
}

// ── Fill role: 2 tiles (128 cells) per block, software-pipelined. ────────
__device__ __forceinline__ void f_pair(float4* __restrict__ out, int b,
                                       int pair, float* S0, float* S1, int* w_s) {
    const int t = threadIdx.x;
    if (t < 32)
        reinterpret_cast<int4*>(w_s)[t] =
            reinterpret_cast<const int4*>(g_winner + b * CELLS)[pair * 32 + t];
    __syncthreads();
    const float4* fp = reinterpret_cast<const float4*>(g_buf[b & 1]);
    float4 g[4];
    f_gather(fp, w_s, g);                  // A(t0)
    f_stage(S0, g);
    __syncthreads();
    f_gather(fp, w_s + 64, g);             // A(t1) — issued before B(t0) work
    f_store(out, b, pair * 32, S0);        // B(t0)
    f_stage(S1, g);
    __syncthreads();
    f_store(out, b, pair * 32 + 16, S1);   // B(t1)
}

// ── L1: winner || T(b0) ──────────────────────────────────────────────────
__global__ void __launch_bounds__(256) pp_wt0(const float4* __restrict__ pts,
                                              const float* __restrict__ feat) {
    __shared__ float S[64 * 65];
    const int bx = blockIdx.x;
    if (bx < W_BLOCKS) w_body(pts, bx);
    else               t_body(feat, 0, bx - W_BLOCKS, S);
}

// ── Lk: T(tb) || F(tb-1), Bresenham-interleaved roles ────────────────────
__global__ void __launch_bounds__(256) pp_tf(const float* __restrict__ feat,
                                             float4* __restrict__ out, int tb) {
    __shared__ float S[2][64 * 65];
    __shared__ int w_s[128];
    const int bx = blockIdx.x;
    int tBefore = (int)(((long long)bx * T_PB) / TF_BLOCKS);
    int tNext   = (int)(((long long)(bx + 1) * T_PB) / TF_BLOCKS);
    if (tNext > tBefore) t_body(feat, tb, tBefore, S[0]);
    else                 f_pair(out, tb - 1, bx - tBefore, S[0], S[1], w_s);
}

// ── L4: F(b3) ────────────────────────────────────────────────────────────
__global__ void __launch_bounds__(256) pp_ftail(float4* __restrict__ out) {
    __shared__ float S[2][64 * 65];
    __shared__ int w_s[128];
    f_pair(out, 3, blockIdx.x, S[0], S[1], w_s);
}

extern "C" void kernel_launch(void* const* d_in, const int* in_sizes, int n_in,
                              void* d_out, int out_size) {
    (void)in_sizes; (void)n_in; (void)out_size;
    const float*  feat = (const float*)d_in[0];   // (B, C, N) f32
    const float4* pts  = (const float4*)d_in[1];  // (B*N, 4)  f32
    float4* out = (float4*)d_out;
    // d_in[2] (voxel_coords) unused by the reference computation.

    pp_initmin<<<I_BLOCKS + M_BLOCKS, 256>>>(pts);       // init || min
    pp_wt0<<<W_BLOCKS + T_PB, 256>>>(pts, feat);         // winner || T(b0)
    for (int b = 1; b < B; ++b)
        pp_tf<<<TF_BLOCKS, 256>>>(feat, out, b);         // T(b) || F(b-1)
    pp_ftail<<<F_PAIRS, 256>>>(out);                     // F(b3)
}